// round 2
// baseline (speedup 1.0000x reference)
#include <cuda_runtime.h>

// ---------------------------------------------------------------------------
// GeometricTerm: geo[n,k,h,w] = GA[nk,h] + GB[nk,w]  (rank-separated position map)
// ---------------------------------------------------------------------------

#define N_ROIS 128
#define CDIM   512
#define KBOX   49
#define ODIM   256
#define HH     64
#define WW     96
#define DDIM   2048               // 4*CDIM
#define NK     (N_ROIS * KBOX)    // 6272
#define GEO_PER_NK (HH * WW)      // 6144

// scratch (device globals: no allocation allowed)
__device__ float g_eps[N_ROIS * DDIM];   // sinusoid(box coords)   [128,2048]
__device__ float g_ex [HH * CDIM];       // sinusoid(h)            [64,512]
__device__ float g_ey [WW * CDIM];       // sinusoid(w)            [96,512]
__device__ float g_v  [N_ROIS * CDIM];   // eps @ V_box^T          [128,512]
__device__ float g_A  [HH * ODIM];       // ex @ W_im[:, :512]^T   [64,256]
__device__ float g_Bm [WW * ODIM];       // ey @ W_im[:, 512:]^T   [96,256]
__device__ float g_box[KBOX * N_ROIS * ODIM];  // [k,n,o]   6272x256
__device__ float g_GA [NK * HH];         // [k*128+n, h]
__device__ float g_GB [NK * WW];         // [k*128+n, w]

// ---------------------------------------------------------------------------
// Kernel 1: sinusoid embeddings for rois (2048/roi), h-axis, w-axis + indices
// ---------------------------------------------------------------------------
__global__ void embed_kernel(const float* __restrict__ rois,
                             float* __restrict__ out_idx, int write_idx)
{
    const float NEG_L = -6.9077552789821368f / 512.0f;  // -ln(1000)/C
    int b = blockIdx.x;
    if (b < N_ROIS) {
        float z0 = rois[b * 5 + 1], z1 = rois[b * 5 + 2];
        float z2 = rois[b * 5 + 3], z3 = rois[b * 5 + 4];
        for (int t = threadIdx.x; t < DDIM; t += blockDim.x) {
            int j = t >> 9;       // which coordinate
            int p = t & 511;      // position inside 512-dim embedding
            float z = (j == 0) ? z0 : (j == 1) ? z1 : (j == 2) ? z2 : z3;
            int  s = (p < 256);
            int  e = s ? (2 * p + 1) : (2 * (p - 256));
            float arg = z * expf(NEG_L * (float)e);
            g_eps[b * DDIM + t] = s ? sinf(arg) : cosf(arg);
        }
        if (threadIdx.x == 0 && write_idx) out_idx[b] = rois[b * 5];
    } else if (b < N_ROIS + HH) {
        int h = b - N_ROIS;
        float z = (float)h;
        for (int p = threadIdx.x; p < CDIM; p += blockDim.x) {
            int s = (p < 256);
            int e = s ? (2 * p + 1) : (2 * (p - 256));
            float arg = z * expf(NEG_L * (float)e);
            g_ex[h * CDIM + p] = s ? sinf(arg) : cosf(arg);
        }
    } else {
        int w = b - N_ROIS - HH;
        float z = (float)w;
        for (int p = threadIdx.x; p < CDIM; p += blockDim.x) {
            int s = (p < 256);
            int e = s ? (2 * p + 1) : (2 * (p - 256));
            float arg = z * expf(NEG_L * (float)e);
            g_ey[w * CDIM + p] = s ? sinf(arg) : cosf(arg);
        }
    }
}

// ---------------------------------------------------------------------------
// Generic NT SGEMM: C[M,N] = A[M,K] (row stride lda) . B[N,K]^T (row stride ldb)
// 64x64 tile, BK=16, 256 threads, 4x4 accum per thread. Batched via blockIdx.z.
// K must be a multiple of 16 and rows float4-aligned (true for all call sites).
// ---------------------------------------------------------------------------
#define BM 64
#define BN 64
#define BK 16

__global__ void sgemm_nt(const float* __restrict__ A, const float* __restrict__ B,
                         float* __restrict__ C,
                         int M, int N, int K, int lda, int ldb, int ldc,
                         long long sA, long long sB, long long sC)
{
    A += (long long)blockIdx.z * sA;
    B += (long long)blockIdx.z * sB;
    C += (long long)blockIdx.z * sC;

    __shared__ float As[BM][BK + 1];
    __shared__ float Bs[BN][BK + 1];

    int tid = threadIdx.x;
    int tx = tid & 15;          // 0..15 -> N direction
    int ty = tid >> 4;          // 0..15 -> M direction
    int row0 = blockIdx.y * BM;
    int col0 = blockIdx.x * BN;

    int lr = tid >> 2;          // 0..63  row loaded by this thread
    int lc = (tid & 3) * 4;     // 0,4,8,12

    float acc[4][4] = {};

    for (int k0 = 0; k0 < K; k0 += BK) {
        int gr = row0 + lr;
        float4 va = make_float4(0.f, 0.f, 0.f, 0.f);
        if (gr < M) va = *(const float4*)(A + (long long)gr * lda + k0 + lc);
        As[lr][lc + 0] = va.x; As[lr][lc + 1] = va.y;
        As[lr][lc + 2] = va.z; As[lr][lc + 3] = va.w;

        int gc = col0 + lr;
        float4 vb = make_float4(0.f, 0.f, 0.f, 0.f);
        if (gc < N) vb = *(const float4*)(B + (long long)gc * ldb + k0 + lc);
        Bs[lr][lc + 0] = vb.x; Bs[lr][lc + 1] = vb.y;
        Bs[lr][lc + 2] = vb.z; Bs[lr][lc + 3] = vb.w;

        __syncthreads();

#pragma unroll
        for (int kk = 0; kk < BK; kk++) {
            float a[4], bb[4];
#pragma unroll
            for (int i = 0; i < 4; i++) a[i]  = As[ty * 4 + i][kk];
#pragma unroll
            for (int j = 0; j < 4; j++) bb[j] = Bs[tx * 4 + j][kk];
#pragma unroll
            for (int i = 0; i < 4; i++)
#pragma unroll
                for (int j = 0; j < 4; j++)
                    acc[i][j] = fmaf(a[i], bb[j], acc[i][j]);
        }
        __syncthreads();
    }

#pragma unroll
    for (int i = 0; i < 4; i++) {
        int r = row0 + ty * 4 + i;
        if (r < M) {
#pragma unroll
            for (int j = 0; j < 4; j++) {
                int c = col0 + tx * 4 + j;
                if (c < N) C[(long long)r * ldc + c] = acc[i][j];
            }
        }
    }
}

// ---------------------------------------------------------------------------
// Kernel 3: geo[nk,h,w] = GA[kn,h] + GB[kn,w]  -- one block per (n,k) tile,
// 6144 contiguous floats per tile, float4 stores.
// ---------------------------------------------------------------------------
__global__ void add_kernel(float* __restrict__ out)
{
    int nk = blockIdx.x;
    int n = nk / KBOX;
    int k = nk - n * KBOX;
    int kn = k * N_ROIS + n;

    __shared__ float ga[HH];
    __shared__ float gb[WW];
    int t = threadIdx.x;
    if (t < HH)                ga[t]       = g_GA[kn * HH + t];
    else if (t < HH + WW)      gb[t - HH]  = g_GB[kn * WW + (t - HH)];
    __syncthreads();

    float4* o = (float4*)(out + (long long)nk * GEO_PER_NK);
    // 1536 float4 per tile; 24 float4 per row of 96
    for (int j = t; j < GEO_PER_NK / 4; j += blockDim.x) {
        int h = j / 24;
        int w = (j - h * 24) * 4;
        float g = ga[h];
        float4 v;
        v.x = g + gb[w + 0];
        v.y = g + gb[w + 1];
        v.z = g + gb[w + 2];
        v.w = g + gb[w + 3];
        o[j] = v;
    }
}

// ---------------------------------------------------------------------------
extern "C" void kernel_launch(void* const* d_in, const int* in_sizes, int n_in,
                              void* d_out, int out_size)
{
    // metadata order: input (unused), rois, V_box, W_box, W_im
    const float* rois  = (const float*)d_in[1];
    const float* V_box = (const float*)d_in[2];
    const float* W_box = (const float*)d_in[3];
    const float* W_im  = (const float*)d_in[4];
    float* out = (float*)d_out;

    const long long n_geo = (long long)NK * GEO_PER_NK;   // 38,535,168
    long long idx_off = (long long)out_size - n_geo;      // expected 128 (indices)
    if (idx_off < 0) idx_off = 0;

    float *eps, *ex, *ey, *v, *Am, *Bm, *box, *GA, *GB;
    cudaGetSymbolAddress((void**)&eps, g_eps);
    cudaGetSymbolAddress((void**)&ex,  g_ex);
    cudaGetSymbolAddress((void**)&ey,  g_ey);
    cudaGetSymbolAddress((void**)&v,   g_v);
    cudaGetSymbolAddress((void**)&Am,  g_A);
    cudaGetSymbolAddress((void**)&Bm,  g_Bm);
    cudaGetSymbolAddress((void**)&box, g_box);
    cudaGetSymbolAddress((void**)&GA,  g_GA);
    cudaGetSymbolAddress((void**)&GB,  g_GB);

    // 1) embeddings (+ indices output)
    embed_kernel<<<N_ROIS + HH + WW, 256>>>(rois, out, idx_off >= N_ROIS ? 1 : 0);

    // 2) v = eps @ V_box^T : [128,512] K=2048
    sgemm_nt<<<dim3(512 / BN, (128 + BM - 1) / BM, 1), 256>>>(
        eps, V_box, v, 128, 512, 2048, 2048, 2048, 512, 0, 0, 0);

    // 3) A = ex @ W_im[:, :512]^T : [64,256] K=512   (ldb = 1024)
    sgemm_nt<<<dim3(256 / BN, 1, 1), 256>>>(
        ex, W_im, Am, 64, 256, 512, 512, 1024, 256, 0, 0, 0);

    // 4) B = ey @ W_im[:, 512:]^T : [96,256] K=512
    sgemm_nt<<<dim3(256 / BN, 2, 1), 256>>>(
        ey, W_im + 512, Bm, 96, 256, 512, 512, 1024, 256, 0, 0, 0);

    // 5) box[k] = v @ W_box[k]^T : 49 x [128,256] K=512 (batched over z)
    sgemm_nt<<<dim3(256 / BN, 2, KBOX), 256>>>(
        v, W_box, box, 128, 256, 512, 512, 512, 256,
        0, (long long)ODIM * CDIM, (long long)N_ROIS * ODIM);

    // 6) GA = box @ A^T : [6272,64] K=256
    sgemm_nt<<<dim3(1, NK / BM, 1), 256>>>(
        box, Am, GA, NK, 64, 256, 256, 256, 64, 0, 0, 0);

    // 7) GB = box @ B^T : [6272,96] K=256
    sgemm_nt<<<dim3(2, NK / BM, 1), 256>>>(
        box, Bm, GB, NK, 96, 256, 256, 256, 96, 0, 0, 0);

    // 8) geo = GA[h] + GB[w] broadcast-add (154 MB write)
    add_kernel<<<NK, 256>>>(out + idx_off);
}

// round 4
// speedup vs baseline: 1.4058x; 1.4058x over previous
#include <cuda_runtime.h>

// ---------------------------------------------------------------------------
// GeometricTerm: geo[n,k,h,w] = G[kn,h] + G[kn,64+w]  (rank-separated pos map)
// R3 = R2 resubmitted verbatim (R2 bench was an infra failure, no data).
// ---------------------------------------------------------------------------

#define N_ROIS 128
#define CDIM   512
#define KBOX   49
#define ODIM   256
#define HH     64
#define WW     96
#define DDIM   2048               // 4*CDIM
#define NK     (N_ROIS * KBOX)    // 6272
#define GEO_PER_NK (HH * WW)      // 6144
#define VSPLIT 16                 // split-K factor for v GEMM
#define ABROWS (HH + WW)          // 160

// scratch (device globals: no allocation allowed)
__device__ float g_eps[N_ROIS * DDIM];            // [128,2048]
__device__ float g_ex [HH * CDIM];                // [64,512]
__device__ float g_ey [WW * CDIM];                // [96,512]
__device__ float g_vp [VSPLIT * N_ROIS * CDIM];   // split-K partials
__device__ float g_v  [N_ROIS * CDIM];            // [128,512]
__device__ float g_AB [ABROWS * ODIM];            // rows 0..63 = A(h), 64..159 = B(w)
__device__ float g_box[KBOX * N_ROIS * ODIM];     // [k,n,o]
__device__ float g_G  [NK * ABROWS];              // [kn, 160]

// ---------------------------------------------------------------------------
// Kernel 1: sinusoid embeddings (+ indices output)
// ---------------------------------------------------------------------------
__global__ void embed_kernel(const float* __restrict__ rois,
                             float* __restrict__ out_idx, int write_idx)
{
    const float NEG_L = -6.9077552789821368f / 512.0f;  // -ln(1000)/C
    int b = blockIdx.x;
    if (b < N_ROIS) {
        float z0 = rois[b * 5 + 1], z1 = rois[b * 5 + 2];
        float z2 = rois[b * 5 + 3], z3 = rois[b * 5 + 4];
        for (int t = threadIdx.x; t < DDIM; t += blockDim.x) {
            int j = t >> 9;
            int p = t & 511;
            float z = (j == 0) ? z0 : (j == 1) ? z1 : (j == 2) ? z2 : z3;
            int  s = (p < 256);
            int  e = s ? (2 * p + 1) : (2 * (p - 256));
            float arg = z * expf(NEG_L * (float)e);
            g_eps[b * DDIM + t] = s ? sinf(arg) : cosf(arg);
        }
        if (threadIdx.x == 0 && write_idx) out_idx[b] = rois[b * 5];
    } else if (b < N_ROIS + HH) {
        int h = b - N_ROIS;
        float z = (float)h;
        for (int p = threadIdx.x; p < CDIM; p += blockDim.x) {
            int s = (p < 256);
            int e = s ? (2 * p + 1) : (2 * (p - 256));
            float arg = z * expf(NEG_L * (float)e);
            g_ex[h * CDIM + p] = s ? sinf(arg) : cosf(arg);
        }
    } else {
        int w = b - N_ROIS - HH;
        float z = (float)w;
        for (int p = threadIdx.x; p < CDIM; p += blockDim.x) {
            int s = (p < 256);
            int e = s ? (2 * p + 1) : (2 * (p - 256));
            float arg = z * expf(NEG_L * (float)e);
            g_ey[w * CDIM + p] = s ? sinf(arg) : cosf(arg);
        }
    }
}

// ---------------------------------------------------------------------------
// NT SGEMM: C[M,N] = A[M,K].B[N,K]^T. 64x64 tile, BK=32, 128 thr, 4x8 micro.
// Smem stored k-major (transposed) so all fragment reads are LDS.128,
// conflict-free. z: batch (sA/sB/sC strides) and/or K-chunk (kz offset).
// Requires: K % 32 == 0, N stores at float4 granularity (N % 8 == 0),
// rows of A and B 16B-aligned.
// ---------------------------------------------------------------------------
#define BM 64
#define BN 64
#define BK 32

__global__ __launch_bounds__(128, 4)
void gemm_nt(const float* __restrict__ A, const float* __restrict__ B,
             float* __restrict__ C,
             int M, int N, int K, int lda, int ldb, int ldc,
             long long sA, long long sB, long long sC, int kz)
{
    int z = blockIdx.z;
    A += (long long)z * sA + (long long)z * kz;   // kz: K-chunk offset (k contiguous)
    B += (long long)z * sB + (long long)z * kz;
    C += (long long)z * sC;

    __shared__ float As[BK][BM];
    __shared__ float Bs[BK][BN];

    int tid  = threadIdx.x;
    int row0 = blockIdx.y * BM;
    int col0 = blockIdx.x * BN;

    // loader role: threads 0..63 load A tile rows, 64..127 load B tile rows
    bool loadB = tid >= 64;
    int  lr    = tid & 63;
    int  grow  = (loadB ? col0 : row0) + lr;
    bool valid = grow < (loadB ? N : M);
    const float* gptr = (loadB ? B : A) + (long long)grow * (loadB ? ldb : lda);
    float (*dst)[BM] = loadB ? Bs : As;

    int tx = tid & 7;           // micro col group (8 cols each)
    int ty = tid >> 3;          // micro row group (4 rows each), 0..15

    float acc[4][8] = {};

    for (int k0 = 0; k0 < K; k0 += BK) {
        float4 r[8];
#pragma unroll
        for (int j = 0; j < 8; j++)
            r[j] = valid ? *(const float4*)(gptr + k0 + j * 4)
                         : make_float4(0.f, 0.f, 0.f, 0.f);
        __syncthreads();   // previous tile's compute done (WAR)
#pragma unroll
        for (int j = 0; j < 8; j++) {
            dst[j * 4 + 0][lr] = r[j].x;
            dst[j * 4 + 1][lr] = r[j].y;
            dst[j * 4 + 2][lr] = r[j].z;
            dst[j * 4 + 3][lr] = r[j].w;
        }
        __syncthreads();

#pragma unroll
        for (int kk = 0; kk < BK; kk++) {
            float4 a  = *(const float4*)&As[kk][ty * 4];
            float4 b0 = *(const float4*)&Bs[kk][tx * 8];
            float4 b1 = *(const float4*)&Bs[kk][tx * 8 + 4];
            float av[4] = {a.x, a.y, a.z, a.w};
            float bv[8] = {b0.x, b0.y, b0.z, b0.w, b1.x, b1.y, b1.z, b1.w};
#pragma unroll
            for (int i = 0; i < 4; i++)
#pragma unroll
                for (int j = 0; j < 8; j++)
                    acc[i][j] = fmaf(av[i], bv[j], acc[i][j]);
        }
    }

    // epilogue: float4 stores, guarded at float4 granularity
#pragma unroll
    for (int i = 0; i < 4; i++) {
        int rrow = row0 + ty * 4 + i;
        if (rrow < M) {
            float* cp = C + (long long)rrow * ldc + col0 + tx * 8;
            if (col0 + tx * 8 + 4 <= N)
                *(float4*)cp = make_float4(acc[i][0], acc[i][1], acc[i][2], acc[i][3]);
            if (col0 + tx * 8 + 8 <= N)
                *(float4*)(cp + 4) = make_float4(acc[i][4], acc[i][5], acc[i][6], acc[i][7]);
        }
    }
}

// ---------------------------------------------------------------------------
// reduce split-K partials: v = sum_z vp[z]
// ---------------------------------------------------------------------------
__global__ void reduce_v_kernel()
{
    int i = blockIdx.x * blockDim.x + threadIdx.x;           // float4 index
    const float4* vp = (const float4*)g_vp;
    float4 s = vp[i];
#pragma unroll
    for (int j = 1; j < VSPLIT; j++) {
        float4 t = vp[i + j * (N_ROIS * CDIM / 4)];
        s.x += t.x; s.y += t.y; s.z += t.z; s.w += t.w;
    }
    ((float4*)g_v)[i] = s;
}

// ---------------------------------------------------------------------------
// geo[nk,h,w] = G[kn,h] + G[kn,64+w]  -- one block per (n,k), float4 stores
// ---------------------------------------------------------------------------
__global__ void add_kernel(float* __restrict__ out)
{
    int nk = blockIdx.x;
    int n = nk / KBOX;
    int k = nk - n * KBOX;
    int kn = k * N_ROIS + n;

    __shared__ float ga[HH];
    __shared__ float gb[WW];
    int t = threadIdx.x;
    if (t < HH)            ga[t]      = g_G[kn * ABROWS + t];
    else if (t < ABROWS)   gb[t - HH] = g_G[kn * ABROWS + t];
    __syncthreads();

    float4* o = (float4*)(out + (long long)nk * GEO_PER_NK);
    for (int j = t; j < GEO_PER_NK / 4; j += blockDim.x) {
        int h = j / 24;                 // 24 float4 per 96-wide row
        int w = (j - h * 24) * 4;
        float g = ga[h];
        float4 v;
        v.x = g + gb[w + 0];
        v.y = g + gb[w + 1];
        v.z = g + gb[w + 2];
        v.w = g + gb[w + 3];
        o[j] = v;
    }
}

// ---------------------------------------------------------------------------
extern "C" void kernel_launch(void* const* d_in, const int* in_sizes, int n_in,
                              void* d_out, int out_size)
{
    // metadata order: input (unused), rois, V_box, W_box, W_im
    const float* rois  = (const float*)d_in[1];
    const float* V_box = (const float*)d_in[2];
    const float* W_box = (const float*)d_in[3];
    const float* W_im  = (const float*)d_in[4];
    float* out = (float*)d_out;

    const long long n_geo = (long long)NK * GEO_PER_NK;   // 38,535,168
    long long idx_off = (long long)out_size - n_geo;
    if (idx_off < 0) idx_off = 0;

    float *eps, *ex, *ey, *vp, *v, *AB, *box, *G;
    cudaGetSymbolAddress((void**)&eps, g_eps);
    cudaGetSymbolAddress((void**)&ex,  g_ex);
    cudaGetSymbolAddress((void**)&ey,  g_ey);
    cudaGetSymbolAddress((void**)&vp,  g_vp);
    cudaGetSymbolAddress((void**)&v,   g_v);
    cudaGetSymbolAddress((void**)&AB,  g_AB);
    cudaGetSymbolAddress((void**)&box, g_box);
    cudaGetSymbolAddress((void**)&G,   g_G);

    // 1) embeddings (+ indices)
    embed_kernel<<<N_ROIS + HH + WW, 256>>>(rois, out, idx_off >= N_ROIS ? 1 : 0);

    // 2) v partials: [128,512] K=2048 split into 16 chunks of 128
    gemm_nt<<<dim3(CDIM / BN, 2, VSPLIT), 128>>>(
        eps, V_box, vp, 128, CDIM, 2048 / VSPLIT, DDIM, DDIM, CDIM,
        0, 0, (long long)N_ROIS * CDIM, 2048 / VSPLIT);

    // 3) v = sum of partials
    reduce_v_kernel<<<(N_ROIS * CDIM / 4) / 256, 256>>>();

    // 4) AB rows 0..63: A-map = ex @ W_im[:, :512]^T  [64,256] K=512
    gemm_nt<<<dim3(ODIM / BN, 1, 1), 128>>>(
        ex, W_im, AB, HH, ODIM, CDIM, CDIM, 2 * CDIM, ODIM, 0, 0, 0, 0);

    // 5) AB rows 64..159: B-map = ey @ W_im[:, 512:]^T  [96,256] K=512
    gemm_nt<<<dim3(ODIM / BN, 2, 1), 128>>>(
        ey, W_im + CDIM, AB + HH * ODIM, WW, ODIM, CDIM, CDIM, 2 * CDIM, ODIM,
        0, 0, 0, 0);

    // 6) box[k] = v @ W_box[k]^T : 49 x [128,256] K=512 (z-batched)
    gemm_nt<<<dim3(ODIM / BN, 2, KBOX), 128>>>(
        v, W_box, box, N_ROIS, ODIM, CDIM, CDIM, CDIM, ODIM,
        0, (long long)ODIM * CDIM, (long long)N_ROIS * ODIM, 0);

    // 7) G = box @ AB^T : [6272,160] K=256
    gemm_nt<<<dim3((ABROWS + BN - 1) / BN, NK / BM, 1), 128>>>(
        box, AB, G, NK, ABROWS, ODIM, ODIM, ODIM, ABROWS, 0, 0, 0, 0);

    // 8) geo = G[:, h] + G[:, 64+w]  (154 MB write)
    add_kernel<<<NK, 256>>>(out + idx_off);
}

// round 5
// speedup vs baseline: 3.4629x; 2.4633x over previous
#include <cuda_runtime.h>
#include <cuda_bf16.h>

// ---------------------------------------------------------------------------
// GeometricTerm: geo[n,k,h,w] = G[kn,h] + G[kn,64+w]
// R4: bf16 hi/lo split tensor-core GEMMs (mma.sync m16n8k16) for v/box/G,
//     fused zero-padded AB GEMM with split-K, latency-bound launches removed.
// ---------------------------------------------------------------------------

#define N_ROIS 128
#define CDIM   512
#define KBOX   49
#define ODIM   256
#define HH     64
#define WW     96
#define DDIM   2048
#define NK     (N_ROIS * KBOX)    // 6272
#define GEO_PER_NK (HH * WW)      // 6144
#define VSPLIT 16
#define ABSPLIT 8
#define ABROWS (HH + WW)          // 160

// scratch (device globals)
__device__ float g_eps [N_ROIS * DDIM];            // [128,2048]
__device__ float g_exy2[ABROWS * 2 * CDIM];        // [160,1024] zero-padded
__device__ float g_vp  [VSPLIT * N_ROIS * CDIM];   // v split-K partials
__device__ float g_v   [N_ROIS * CDIM];            // [128,512]
__device__ float g_ABp [ABSPLIT * ABROWS * ODIM];  // AB split-K partials
__device__ float g_AB  [ABROWS * ODIM];            // [160,256]
__device__ float g_box [KBOX * N_ROIS * ODIM];     // [k,n,o]
__device__ float g_G   [NK * ABROWS];              // [kn,160]

// ---------------------------------------------------------------------------
// sinusoid embeddings + zero-padded exy2 + indices
// ---------------------------------------------------------------------------
__global__ void embed_kernel(const float* __restrict__ rois,
                             float* __restrict__ out_idx, int write_idx)
{
    const float NEG_L = -6.9077552789821368f / 512.0f;  // -ln(1000)/C
    int b = blockIdx.x;
    if (b < N_ROIS) {
        float z0 = rois[b * 5 + 1], z1 = rois[b * 5 + 2];
        float z2 = rois[b * 5 + 3], z3 = rois[b * 5 + 4];
        for (int t = threadIdx.x; t < DDIM; t += blockDim.x) {
            int j = t >> 9;
            int p = t & 511;
            float z = (j == 0) ? z0 : (j == 1) ? z1 : (j == 2) ? z2 : z3;
            int  s = (p < 256);
            int  e = s ? (2 * p + 1) : (2 * (p - 256));
            float arg = z * expf(NEG_L * (float)e);
            g_eps[b * DDIM + t] = s ? sinf(arg) : cosf(arg);
        }
        if (threadIdx.x == 0 && write_idx) out_idx[b] = rois[b * 5];
    } else if (b < N_ROIS + HH) {
        int h = b - N_ROIS;
        float z = (float)h;
        for (int p = threadIdx.x; p < CDIM; p += blockDim.x) {
            int s = (p < 256);
            int e = s ? (2 * p + 1) : (2 * (p - 256));
            float arg = z * expf(NEG_L * (float)e);
            g_exy2[h * (2 * CDIM) + p] = s ? sinf(arg) : cosf(arg);
            g_exy2[h * (2 * CDIM) + CDIM + p] = 0.f;   // pad
        }
    } else {
        int w = b - N_ROIS - HH;
        float z = (float)w;
        for (int p = threadIdx.x; p < CDIM; p += blockDim.x) {
            int s = (p < 256);
            int e = s ? (2 * p + 1) : (2 * (p - 256));
            float arg = z * expf(NEG_L * (float)e);
            g_exy2[(HH + w) * (2 * CDIM) + p] = 0.f;   // pad
            g_exy2[(HH + w) * (2 * CDIM) + CDIM + p] = s ? sinf(arg) : cosf(arg);
        }
    }
}

// ---------------------------------------------------------------------------
// bf16 split helpers + mma
// ---------------------------------------------------------------------------
__device__ __forceinline__ void split_pack(float x0, float x1,
                                           unsigned& h, unsigned& l)
{
    __nv_bfloat162 hh = __floats2bfloat162_rn(x0, x1);
    float r0 = x0 - __low2float(hh);
    float r1 = x1 - __high2float(hh);
    __nv_bfloat162 ll = __floats2bfloat162_rn(r0, r1);
    h = reinterpret_cast<unsigned&>(hh);
    l = reinterpret_cast<unsigned&>(ll);
}

__device__ __forceinline__ void mma16816(float c[4], const unsigned a[4],
                                         const unsigned b[2])
{
    asm volatile(
        "mma.sync.aligned.m16n8k16.row.col.f32.bf16.bf16.f32 "
        "{%0,%1,%2,%3}, {%4,%5,%6,%7}, {%8,%9}, {%0,%1,%2,%3};"
        : "+f"(c[0]), "+f"(c[1]), "+f"(c[2]), "+f"(c[3])
        : "r"(a[0]), "r"(a[1]), "r"(a[2]), "r"(a[3]), "r"(b[0]), "r"(b[1]));
}

// ---------------------------------------------------------------------------
// NT GEMM via bf16 hi/lo split mma: C[M,N] = A[M,K].B[N,K]^T, fp32 in/out.
// Block tile BM x BN (BM,BN exact divisors of M,N), BK=32, 256 threads.
// Warp grid WM x WN, warp tile 32 x (BN/WN), NI = BN/WN/8 n8-frags.
// z: A += z*kz (split-K), B += z*sB + z*kz, C += z*sC.
// smem pitch 20 u32 (40 bf16) per row -> conflict-free frag loads.
// ---------------------------------------------------------------------------
template<int BM, int BN, int WM, int WN>
__global__ __launch_bounds__(256, 2)
void mma_nt(const float* __restrict__ A, const float* __restrict__ B,
            float* __restrict__ C, int K, int lda, int ldb, int ldc,
            long long sB, long long sC, int kz)
{
    constexpr int NI = BN / WN / 8;   // n8 frags per warp
    constexpr int P  = 20;            // smem pitch in u32 (BK/2 + 4 pad)

    int z = blockIdx.z;
    A += (long long)z * kz;
    B += (long long)z * sB + (long long)z * kz;
    C += (long long)z * sC;

    __shared__ unsigned As_h[BM * P], As_l[BM * P];
    __shared__ unsigned Bs_h[BN * P], Bs_l[BN * P];

    int tid  = threadIdx.x;
    int lane = tid & 31, wid = tid >> 5;
    int wm = wid % WM, wn = wid / WM;
    int g = lane >> 2, tg = lane & 3;
    int row0 = blockIdx.y * BM;
    int col0 = blockIdx.x * BN;

    float acc[2][NI][4] = {};

    for (int k0 = 0; k0 < K; k0 += 32) {
        // prefetch chunk (A: BM x 32, B: BN x 32) as float4
        float4 ra[BM * 8 / 256], rb[BN * 8 / 256];
#pragma unroll
        for (int j = 0; j < BM * 8 / 256; j++) {
            int i = tid + j * 256, r = i >> 3, c4 = i & 7;
            ra[j] = *(const float4*)(A + (long long)(row0 + r) * lda + k0 + c4 * 4);
        }
#pragma unroll
        for (int j = 0; j < BN * 8 / 256; j++) {
            int i = tid + j * 256, r = i >> 3, c4 = i & 7;
            rb[j] = *(const float4*)(B + (long long)(col0 + r) * ldb + k0 + c4 * 4);
        }
        __syncthreads();   // WAR: previous chunk's compute done
#pragma unroll
        for (int j = 0; j < BM * 8 / 256; j++) {
            int i = tid + j * 256, r = i >> 3, c4 = i & 7;
            unsigned h0, l0, h1, l1;
            split_pack(ra[j].x, ra[j].y, h0, l0);
            split_pack(ra[j].z, ra[j].w, h1, l1);
            As_h[r * P + c4 * 2] = h0; As_h[r * P + c4 * 2 + 1] = h1;
            As_l[r * P + c4 * 2] = l0; As_l[r * P + c4 * 2 + 1] = l1;
        }
#pragma unroll
        for (int j = 0; j < BN * 8 / 256; j++) {
            int i = tid + j * 256, r = i >> 3, c4 = i & 7;
            unsigned h0, l0, h1, l1;
            split_pack(rb[j].x, rb[j].y, h0, l0);
            split_pack(rb[j].z, rb[j].w, h1, l1);
            Bs_h[r * P + c4 * 2] = h0; Bs_h[r * P + c4 * 2 + 1] = h1;
            Bs_l[r * P + c4 * 2] = l0; Bs_l[r * P + c4 * 2 + 1] = l1;
        }
        __syncthreads();

#pragma unroll
        for (int ks = 0; ks < 2; ks++) {
            unsigned ah[2][4], al[2][4], bh[NI][2], bl[NI][2];
#pragma unroll
            for (int mi = 0; mi < 2; mi++) {
                int base = (wm * 32 + mi * 16 + g) * P + ks * 8 + tg;
                ah[mi][0] = As_h[base];           ah[mi][1] = As_h[base + 8 * P];
                ah[mi][2] = As_h[base + 4];       ah[mi][3] = As_h[base + 8 * P + 4];
                al[mi][0] = As_l[base];           al[mi][1] = As_l[base + 8 * P];
                al[mi][2] = As_l[base + 4];       al[mi][3] = As_l[base + 8 * P + 4];
            }
#pragma unroll
            for (int ni = 0; ni < NI; ni++) {
                int base = (wn * (BN / WN) + ni * 8 + g) * P + ks * 8 + tg;
                bh[ni][0] = Bs_h[base]; bh[ni][1] = Bs_h[base + 4];
                bl[ni][0] = Bs_l[base]; bl[ni][1] = Bs_l[base + 4];
            }
#pragma unroll
            for (int mi = 0; mi < 2; mi++)
#pragma unroll
                for (int ni = 0; ni < NI; ni++) {
                    mma16816(acc[mi][ni], ah[mi], bh[ni]);   // hi*hi
                    mma16816(acc[mi][ni], ah[mi], bl[ni]);   // hi*lo
                    mma16816(acc[mi][ni], al[mi], bh[ni]);   // lo*hi
                }
        }
    }

    // epilogue: float2 stores
#pragma unroll
    for (int mi = 0; mi < 2; mi++) {
        int r = row0 + wm * 32 + mi * 16 + g;
#pragma unroll
        for (int ni = 0; ni < NI; ni++) {
            int c = col0 + wn * (BN / WN) + ni * 8 + tg * 2;
            *(float2*)(C + (long long)r * ldc + c) =
                make_float2(acc[mi][ni][0], acc[mi][ni][1]);
            *(float2*)(C + (long long)(r + 8) * ldc + c) =
                make_float2(acc[mi][ni][2], acc[mi][ni][3]);
        }
    }
}

// ---------------------------------------------------------------------------
// fp32 NT SGEMM (for the small AB GEMM; M=160 needs guards). 64x64, BK=32.
// ---------------------------------------------------------------------------
__global__ __launch_bounds__(128, 4)
void gemm_nt(const float* __restrict__ A, const float* __restrict__ B,
             float* __restrict__ C,
             int M, int N, int K, int lda, int ldb, int ldc,
             long long sC, int kz)
{
    int z = blockIdx.z;
    A += (long long)z * kz;
    B += (long long)z * kz;
    C += (long long)z * sC;

    __shared__ float As[32][64];
    __shared__ float Bs[32][64];

    int tid  = threadIdx.x;
    int row0 = blockIdx.y * 64;
    int col0 = blockIdx.x * 64;

    bool loadB = tid >= 64;
    int  lr    = tid & 63;
    int  grow  = (loadB ? col0 : row0) + lr;
    bool valid = grow < (loadB ? N : M);
    const float* gptr = (loadB ? B : A) + (long long)grow * (loadB ? ldb : lda);
    float (*dst)[64] = loadB ? Bs : As;

    int tx = tid & 7;
    int ty = tid >> 3;

    float acc[4][8] = {};

    for (int k0 = 0; k0 < K; k0 += 32) {
        float4 r[8];
#pragma unroll
        for (int j = 0; j < 8; j++)
            r[j] = valid ? *(const float4*)(gptr + k0 + j * 4)
                         : make_float4(0.f, 0.f, 0.f, 0.f);
        __syncthreads();
#pragma unroll
        for (int j = 0; j < 8; j++) {
            dst[j * 4 + 0][lr] = r[j].x;
            dst[j * 4 + 1][lr] = r[j].y;
            dst[j * 4 + 2][lr] = r[j].z;
            dst[j * 4 + 3][lr] = r[j].w;
        }
        __syncthreads();

#pragma unroll
        for (int kk = 0; kk < 32; kk++) {
            float4 a  = *(const float4*)&As[kk][ty * 4];
            float4 b0 = *(const float4*)&Bs[kk][tx * 8];
            float4 b1 = *(const float4*)&Bs[kk][tx * 8 + 4];
            float av[4] = {a.x, a.y, a.z, a.w};
            float bv[8] = {b0.x, b0.y, b0.z, b0.w, b1.x, b1.y, b1.z, b1.w};
#pragma unroll
            for (int i = 0; i < 4; i++)
#pragma unroll
                for (int j = 0; j < 8; j++)
                    acc[i][j] = fmaf(av[i], bv[j], acc[i][j]);
        }
    }

#pragma unroll
    for (int i = 0; i < 4; i++) {
        int rrow = row0 + ty * 4 + i;
        if (rrow < M) {
            float* cp = C + (long long)rrow * ldc + col0 + tx * 8;
            *(float4*)cp = make_float4(acc[i][0], acc[i][1], acc[i][2], acc[i][3]);
            *(float4*)(cp + 4) = make_float4(acc[i][4], acc[i][5], acc[i][6], acc[i][7]);
        }
    }
}

// ---------------------------------------------------------------------------
// split-K reductions
// ---------------------------------------------------------------------------
__global__ void reduce_v_kernel()
{
    int i = blockIdx.x * blockDim.x + threadIdx.x;
    const float4* vp = (const float4*)g_vp;
    float4 s = vp[i];
#pragma unroll
    for (int j = 1; j < VSPLIT; j++) {
        float4 t = vp[i + j * (N_ROIS * CDIM / 4)];
        s.x += t.x; s.y += t.y; s.z += t.z; s.w += t.w;
    }
    ((float4*)g_v)[i] = s;
}

__global__ void reduce_ab_kernel()
{
    int i = blockIdx.x * blockDim.x + threadIdx.x;
    const float4* p = (const float4*)g_ABp;
    float4 s = p[i];
#pragma unroll
    for (int j = 1; j < ABSPLIT; j++) {
        float4 t = p[i + j * (ABROWS * ODIM / 4)];
        s.x += t.x; s.y += t.y; s.z += t.z; s.w += t.w;
    }
    ((float4*)g_AB)[i] = s;
}

// ---------------------------------------------------------------------------
// geo[nk,h,w] = G[kn,h] + G[kn,64+w]
// ---------------------------------------------------------------------------
__global__ void add_kernel(float* __restrict__ out)
{
    int nk = blockIdx.x;
    int n = nk / KBOX;
    int k = nk - n * KBOX;
    int kn = k * N_ROIS + n;

    __shared__ float ga[HH];
    __shared__ float gb[WW];
    int t = threadIdx.x;
    if (t < HH)            ga[t]      = g_G[kn * ABROWS + t];
    else if (t < ABROWS)   gb[t - HH] = g_G[kn * ABROWS + t];
    __syncthreads();

    float4* o = (float4*)(out + (long long)nk * GEO_PER_NK);
    for (int j = t; j < GEO_PER_NK / 4; j += blockDim.x) {
        int h = j / 24;
        int w = (j - h * 24) * 4;
        float g = ga[h];
        float4 v;
        v.x = g + gb[w + 0];
        v.y = g + gb[w + 1];
        v.z = g + gb[w + 2];
        v.w = g + gb[w + 3];
        o[j] = v;
    }
}

// ---------------------------------------------------------------------------
extern "C" void kernel_launch(void* const* d_in, const int* in_sizes, int n_in,
                              void* d_out, int out_size)
{
    const float* rois  = (const float*)d_in[1];
    const float* V_box = (const float*)d_in[2];
    const float* W_box = (const float*)d_in[3];
    const float* W_im  = (const float*)d_in[4];
    float* out = (float*)d_out;

    const long long n_geo = (long long)NK * GEO_PER_NK;   // 38,535,168
    long long idx_off = (long long)out_size - n_geo;
    if (idx_off < 0) idx_off = 0;

    float *eps, *exy2, *vp, *v, *ABp, *AB, *box, *G;
    cudaGetSymbolAddress((void**)&eps,  g_eps);
    cudaGetSymbolAddress((void**)&exy2, g_exy2);
    cudaGetSymbolAddress((void**)&vp,   g_vp);
    cudaGetSymbolAddress((void**)&v,    g_v);
    cudaGetSymbolAddress((void**)&ABp,  g_ABp);
    cudaGetSymbolAddress((void**)&AB,   g_AB);
    cudaGetSymbolAddress((void**)&box,  g_box);
    cudaGetSymbolAddress((void**)&G,    g_G);

    // 1) embeddings (+ indices)
    embed_kernel<<<N_ROIS + HH + WW, 256>>>(rois, out, idx_off >= N_ROIS ? 1 : 0);

    // 2) v partials: [128,512] = eps @ V_box^T, K=2048 split 16x128 (128 blocks)
    mma_nt<128, 64, 4, 2><<<dim3(CDIM / 64, 1, VSPLIT), 256>>>(
        eps, V_box, vp, 2048 / VSPLIT, DDIM, DDIM, CDIM,
        0, (long long)N_ROIS * CDIM, 2048 / VSPLIT);

    // 3) v = sum of partials
    reduce_v_kernel<<<(N_ROIS * CDIM / 4) / 256, 256>>>();

    // 4) AB partials: [160,256] = exy2 @ W_im^T, K=1024 split 8x128 (96 blocks)
    gemm_nt<<<dim3(ODIM / 64, 3, ABSPLIT), 128>>>(
        exy2, W_im, ABp, ABROWS, ODIM, 1024 / ABSPLIT, 2 * CDIM, 2 * CDIM, ODIM,
        (long long)ABROWS * ODIM, 1024 / ABSPLIT);

    // 5) AB = sum of partials
    reduce_ab_kernel<<<(ABROWS * ODIM / 4) / 256, 256>>>();

    // 6) box[k] = v @ W_box[k]^T : 49 x [128,256], K=512 (196 blocks)
    mma_nt<128, 64, 4, 2><<<dim3(ODIM / 64, 1, KBOX), 256>>>(
        v, W_box, box, CDIM, CDIM, CDIM, ODIM,
        (long long)ODIM * CDIM, (long long)N_ROIS * ODIM, 0);

    // 7) G = box @ AB^T : [6272,160], K=256 (98 blocks)
    mma_nt<64, 160, 2, 4><<<dim3(1, NK / 64, 1), 256>>>(
        box, AB, G, ODIM, ODIM, ODIM, ABROWS, 0, 0, 0);

    // 8) geo = G[:, h] + G[:, 64+w] (154 MB write)
    add_kernel<<<NK, 256>>>(out + idx_off);
}

// round 8
// speedup vs baseline: 3.4707x; 1.0022x over previous
#include <cuda_runtime.h>
#include <cuda_bf16.h>

// ---------------------------------------------------------------------------
// GeometricTerm: geo[n,k,h,w] = G[kn,h] + G[kn,64+w]
// R7: R4 (known-good) + fast-math embeddings + ABSPLIT 16.
// Deliberately avoids the mma_nt<32,64,1,8> instantiation from R5/R6
// (twice-failed container; source weakly implicated).
// ---------------------------------------------------------------------------

#define N_ROIS 128
#define CDIM   512
#define KBOX   49
#define ODIM   256
#define HH     64
#define WW     96
#define DDIM   2048
#define NK     (N_ROIS * KBOX)    // 6272
#define GEO_PER_NK (HH * WW)      // 6144
#define VSPLIT 16
#define ABSPLIT 16
#define ABROWS (HH + WW)          // 160

// scratch (device globals)
__device__ float g_eps [N_ROIS * DDIM];            // [128,2048]
__device__ float g_exy2[ABROWS * 2 * CDIM];        // [160,1024] zero-padded
__device__ float g_vp  [VSPLIT * N_ROIS * CDIM];   // v split-K partials
__device__ float g_v   [N_ROIS * CDIM];            // [128,512]
__device__ float g_ABp [ABSPLIT * ABROWS * ODIM];  // AB split-K partials
__device__ float g_AB  [ABROWS * ODIM];            // [160,256]
__device__ float g_box [KBOX * N_ROIS * ODIM];     // [k,n,o]
__device__ float g_G   [NK * ABROWS];              // [kn,160]

// ---------------------------------------------------------------------------
// sinusoid embeddings + zero-padded exy2 + indices (fast-math MUFU path)
// ---------------------------------------------------------------------------
__global__ void embed_kernel(const float* __restrict__ rois,
                             float* __restrict__ out_idx, int write_idx)
{
    const float NEG_L = -6.9077552789821368f / 512.0f;  // -ln(1000)/C
    int b = blockIdx.x;
    if (b < N_ROIS) {
        float z0 = rois[b * 5 + 1], z1 = rois[b * 5 + 2];
        float z2 = rois[b * 5 + 3], z3 = rois[b * 5 + 4];
        for (int t = threadIdx.x; t < DDIM; t += blockDim.x) {
            int j = t >> 9;
            int p = t & 511;
            float z = (j == 0) ? z0 : (j == 1) ? z1 : (j == 2) ? z2 : z3;
            int  s = (p < 256);
            int  e = s ? (2 * p + 1) : (2 * (p - 256));
            float arg = z * __expf(NEG_L * (float)e);
            g_eps[b * DDIM + t] = s ? __sinf(arg) : __cosf(arg);
        }
        if (threadIdx.x == 0 && write_idx) out_idx[b] = rois[b * 5];
    } else if (b < N_ROIS + HH) {
        int h = b - N_ROIS;
        float z = (float)h;
        for (int p = threadIdx.x; p < CDIM; p += blockDim.x) {
            int s = (p < 256);
            int e = s ? (2 * p + 1) : (2 * (p - 256));
            float arg = z * __expf(NEG_L * (float)e);
            g_exy2[h * (2 * CDIM) + p] = s ? __sinf(arg) : __cosf(arg);
            g_exy2[h * (2 * CDIM) + CDIM + p] = 0.f;   // pad
        }
    } else {
        int w = b - N_ROIS - HH;
        float z = (float)w;
        for (int p = threadIdx.x; p < CDIM; p += blockDim.x) {
            int s = (p < 256);
            int e = s ? (2 * p + 1) : (2 * (p - 256));
            float arg = z * __expf(NEG_L * (float)e);
            g_exy2[(HH + w) * (2 * CDIM) + p] = 0.f;   // pad
            g_exy2[(HH + w) * (2 * CDIM) + CDIM + p] = s ? __sinf(arg) : __cosf(arg);
        }
    }
}

// ---------------------------------------------------------------------------
// bf16 split helpers + mma
// ---------------------------------------------------------------------------
__device__ __forceinline__ void split_pack(float x0, float x1,
                                           unsigned& h, unsigned& l)
{
    __nv_bfloat162 hh = __floats2bfloat162_rn(x0, x1);
    float r0 = x0 - __low2float(hh);
    float r1 = x1 - __high2float(hh);
    __nv_bfloat162 ll = __floats2bfloat162_rn(r0, r1);
    h = reinterpret_cast<unsigned&>(hh);
    l = reinterpret_cast<unsigned&>(ll);
}

__device__ __forceinline__ void mma16816(float c[4], const unsigned a[4],
                                         const unsigned b[2])
{
    asm volatile(
        "mma.sync.aligned.m16n8k16.row.col.f32.bf16.bf16.f32 "
        "{%0,%1,%2,%3}, {%4,%5,%6,%7}, {%8,%9}, {%0,%1,%2,%3};"
        : "+f"(c[0]), "+f"(c[1]), "+f"(c[2]), "+f"(c[3])
        : "r"(a[0]), "r"(a[1]), "r"(a[2]), "r"(a[3]), "r"(b[0]), "r"(b[1]));
}

// ---------------------------------------------------------------------------
// NT GEMM via bf16 hi/lo split mma: C[M,N] = A[M,K].B[N,K]^T, fp32 in/out.
// Block tile BM x BN (exact divisors of M,N), BK=32, 256 threads.
// Warp grid WM x WN (WM*WN=8); warp tile 32 rows x BN/WN cols.
// z: A += z*kz (split-K), B += z*sB + z*kz, C += z*sC.
// ---------------------------------------------------------------------------
template<int BM, int BN, int WM, int WN>
__global__ __launch_bounds__(256, 2)
void mma_nt(const float* __restrict__ A, const float* __restrict__ B,
            float* __restrict__ C, int K, int lda, int ldb, int ldc,
            long long sB, long long sC, int kz)
{
    constexpr int NI = BN / WN / 8;   // n8 frags per warp
    constexpr int P  = 20;            // smem pitch in u32 (BK/2 + 4 pad)

    int z = blockIdx.z;
    A += (long long)z * kz;
    B += (long long)z * sB + (long long)z * kz;
    C += (long long)z * sC;

    __shared__ unsigned As_h[BM * P], As_l[BM * P];
    __shared__ unsigned Bs_h[BN * P], Bs_l[BN * P];

    int tid  = threadIdx.x;
    int lane = tid & 31, wid = tid >> 5;
    int wm = wid % WM, wn = wid / WM;
    int g = lane >> 2, tg = lane & 3;
    int row0 = blockIdx.y * BM;
    int col0 = blockIdx.x * BN;

    float acc[2][NI][4] = {};

    for (int k0 = 0; k0 < K; k0 += 32) {
        // prefetch chunk (A: BM x 32, B: BN x 32) as float4
        float4 ra[BM * 8 / 256], rb[BN * 8 / 256];
#pragma unroll
        for (int j = 0; j < BM * 8 / 256; j++) {
            int i = tid + j * 256, r = i >> 3, c4 = i & 7;
            ra[j] = *(const float4*)(A + (long long)(row0 + r) * lda + k0 + c4 * 4);
        }
#pragma unroll
        for (int j = 0; j < BN * 8 / 256; j++) {
            int i = tid + j * 256, r = i >> 3, c4 = i & 7;
            rb[j] = *(const float4*)(B + (long long)(col0 + r) * ldb + k0 + c4 * 4);
        }
        __syncthreads();   // WAR: previous chunk's compute done
#pragma unroll
        for (int j = 0; j < BM * 8 / 256; j++) {
            int i = tid + j * 256, r = i >> 3, c4 = i & 7;
            unsigned h0, l0, h1, l1;
            split_pack(ra[j].x, ra[j].y, h0, l0);
            split_pack(ra[j].z, ra[j].w, h1, l1);
            As_h[r * P + c4 * 2] = h0; As_h[r * P + c4 * 2 + 1] = h1;
            As_l[r * P + c4 * 2] = l0; As_l[r * P + c4 * 2 + 1] = l1;
        }
#pragma unroll
        for (int j = 0; j < BN * 8 / 256; j++) {
            int i = tid + j * 256, r = i >> 3, c4 = i & 7;
            unsigned h0, l0, h1, l1;
            split_pack(rb[j].x, rb[j].y, h0, l0);
            split_pack(rb[j].z, rb[j].w, h1, l1);
            Bs_h[r * P + c4 * 2] = h0; Bs_h[r * P + c4 * 2 + 1] = h1;
            Bs_l[r * P + c4 * 2] = l0; Bs_l[r * P + c4 * 2 + 1] = l1;
        }
        __syncthreads();

#pragma unroll
        for (int ks = 0; ks < 2; ks++) {
            unsigned ah[2][4], al[2][4], bh[NI][2], bl[NI][2];
#pragma unroll
            for (int mi = 0; mi < 2; mi++) {
                int base = (wm * 32 + mi * 16 + g) * P + ks * 8 + tg;
                ah[mi][0] = As_h[base];           ah[mi][1] = As_h[base + 8 * P];
                ah[mi][2] = As_h[base + 4];       ah[mi][3] = As_h[base + 8 * P + 4];
                al[mi][0] = As_l[base];           al[mi][1] = As_l[base + 8 * P];
                al[mi][2] = As_l[base + 4];       al[mi][3] = As_l[base + 8 * P + 4];
            }
#pragma unroll
            for (int ni = 0; ni < NI; ni++) {
                int base = (wn * (BN / WN) + ni * 8 + g) * P + ks * 8 + tg;
                bh[ni][0] = Bs_h[base]; bh[ni][1] = Bs_h[base + 4];
                bl[ni][0] = Bs_l[base]; bl[ni][1] = Bs_l[base + 4];
            }
#pragma unroll
            for (int mi = 0; mi < 2; mi++)
#pragma unroll
                for (int ni = 0; ni < NI; ni++) {
                    mma16816(acc[mi][ni], ah[mi], bh[ni]);   // hi*hi
                    mma16816(acc[mi][ni], ah[mi], bl[ni]);   // hi*lo
                    mma16816(acc[mi][ni], al[mi], bh[ni]);   // lo*hi
                }
        }
    }

    // epilogue: float2 stores
#pragma unroll
    for (int mi = 0; mi < 2; mi++) {
        int r = row0 + wm * 32 + mi * 16 + g;
#pragma unroll
        for (int ni = 0; ni < NI; ni++) {
            int c = col0 + wn * (BN / WN) + ni * 8 + tg * 2;
            *(float2*)(C + (long long)r * ldc + c) =
                make_float2(acc[mi][ni][0], acc[mi][ni][1]);
            *(float2*)(C + (long long)(r + 8) * ldc + c) =
                make_float2(acc[mi][ni][2], acc[mi][ni][3]);
        }
    }
}

// ---------------------------------------------------------------------------
// fp32 NT SGEMM (AB stage; M=160 needs guards). 64x64, BK=32, 128 threads.
// ---------------------------------------------------------------------------
__global__ __launch_bounds__(128, 4)
void gemm_nt(const float* __restrict__ A, const float* __restrict__ B,
             float* __restrict__ C,
             int M, int N, int K, int lda, int ldb, int ldc,
             long long sC, int kz)
{
    int z = blockIdx.z;
    A += (long long)z * kz;
    B += (long long)z * kz;
    C += (long long)z * sC;

    __shared__ float As[32][64];
    __shared__ float Bs[32][64];

    int tid  = threadIdx.x;
    int row0 = blockIdx.y * 64;
    int col0 = blockIdx.x * 64;

    bool loadB = tid >= 64;
    int  lr    = tid & 63;
    int  grow  = (loadB ? col0 : row0) + lr;
    bool valid = grow < (loadB ? N : M);
    const float* gptr = (loadB ? B : A) + (long long)grow * (loadB ? ldb : lda);
    float (*dst)[64] = loadB ? Bs : As;

    int tx = tid & 7;
    int ty = tid >> 3;

    float acc[4][8] = {};

    for (int k0 = 0; k0 < K; k0 += 32) {
        float4 r[8];
#pragma unroll
        for (int j = 0; j < 8; j++)
            r[j] = valid ? *(const float4*)(gptr + k0 + j * 4)
                         : make_float4(0.f, 0.f, 0.f, 0.f);
        __syncthreads();
#pragma unroll
        for (int j = 0; j < 8; j++) {
            dst[j * 4 + 0][lr] = r[j].x;
            dst[j * 4 + 1][lr] = r[j].y;
            dst[j * 4 + 2][lr] = r[j].z;
            dst[j * 4 + 3][lr] = r[j].w;
        }
        __syncthreads();

#pragma unroll
        for (int kk = 0; kk < 32; kk++) {
            float4 a  = *(const float4*)&As[kk][ty * 4];
            float4 b0 = *(const float4*)&Bs[kk][tx * 8];
            float4 b1 = *(const float4*)&Bs[kk][tx * 8 + 4];
            float av[4] = {a.x, a.y, a.z, a.w};
            float bv[8] = {b0.x, b0.y, b0.z, b0.w, b1.x, b1.y, b1.z, b1.w};
#pragma unroll
            for (int i = 0; i < 4; i++)
#pragma unroll
                for (int j = 0; j < 8; j++)
                    acc[i][j] = fmaf(av[i], bv[j], acc[i][j]);
        }
    }

#pragma unroll
    for (int i = 0; i < 4; i++) {
        int rrow = row0 + ty * 4 + i;
        if (rrow < M) {
            float* cp = C + (long long)rrow * ldc + col0 + tx * 8;
            *(float4*)cp = make_float4(acc[i][0], acc[i][1], acc[i][2], acc[i][3]);
            *(float4*)(cp + 4) = make_float4(acc[i][4], acc[i][5], acc[i][6], acc[i][7]);
        }
    }
}

// ---------------------------------------------------------------------------
// split-K reductions
// ---------------------------------------------------------------------------
__global__ void reduce_v_kernel()
{
    int i = blockIdx.x * blockDim.x + threadIdx.x;
    const float4* vp = (const float4*)g_vp;
    float4 s = vp[i];
#pragma unroll
    for (int j = 1; j < VSPLIT; j++) {
        float4 t = vp[i + j * (N_ROIS * CDIM / 4)];
        s.x += t.x; s.y += t.y; s.z += t.z; s.w += t.w;
    }
    ((float4*)g_v)[i] = s;
}

__global__ void reduce_ab_kernel()
{
    int i = blockIdx.x * blockDim.x + threadIdx.x;
    const float4* p = (const float4*)g_ABp;
    float4 s = p[i];
#pragma unroll
    for (int j = 1; j < ABSPLIT; j++) {
        float4 t = p[i + j * (ABROWS * ODIM / 4)];
        s.x += t.x; s.y += t.y; s.z += t.z; s.w += t.w;
    }
    ((float4*)g_AB)[i] = s;
}

// ---------------------------------------------------------------------------
// geo[nk,h,w] = G[kn,h] + G[kn,64+w]
// ---------------------------------------------------------------------------
__global__ void add_kernel(float* __restrict__ out)
{
    int nk = blockIdx.x;
    int n = nk / KBOX;
    int k = nk - n * KBOX;
    int kn = k * N_ROIS + n;

    __shared__ float ga[HH];
    __shared__ float gb[WW];
    int t = threadIdx.x;
    if (t < HH)            ga[t]      = g_G[kn * ABROWS + t];
    else if (t < ABROWS)   gb[t - HH] = g_G[kn * ABROWS + t];
    __syncthreads();

    float4* o = (float4*)(out + (long long)nk * GEO_PER_NK);
    for (int j = t; j < GEO_PER_NK / 4; j += blockDim.x) {
        int h = j / 24;
        int w = (j - h * 24) * 4;
        float g = ga[h];
        float4 v;
        v.x = g + gb[w + 0];
        v.y = g + gb[w + 1];
        v.z = g + gb[w + 2];
        v.w = g + gb[w + 3];
        o[j] = v;
    }
}

// ---------------------------------------------------------------------------
extern "C" void kernel_launch(void* const* d_in, const int* in_sizes, int n_in,
                              void* d_out, int out_size)
{
    const float* rois  = (const float*)d_in[1];
    const float* V_box = (const float*)d_in[2];
    const float* W_box = (const float*)d_in[3];
    const float* W_im  = (const float*)d_in[4];
    float* out = (float*)d_out;

    const long long n_geo = (long long)NK * GEO_PER_NK;   // 38,535,168
    long long idx_off = (long long)out_size - n_geo;
    if (idx_off < 0) idx_off = 0;

    float *eps, *exy2, *vp, *v, *ABp, *AB, *box, *G;
    cudaGetSymbolAddress((void**)&eps,  g_eps);
    cudaGetSymbolAddress((void**)&exy2, g_exy2);
    cudaGetSymbolAddress((void**)&vp,   g_vp);
    cudaGetSymbolAddress((void**)&v,    g_v);
    cudaGetSymbolAddress((void**)&ABp,  g_ABp);
    cudaGetSymbolAddress((void**)&AB,   g_AB);
    cudaGetSymbolAddress((void**)&box,  g_box);
    cudaGetSymbolAddress((void**)&G,    g_G);

    // 1) embeddings (+ indices)
    embed_kernel<<<N_ROIS + HH + WW, 256>>>(rois, out, idx_off >= N_ROIS ? 1 : 0);

    // 2) v partials: [128,512] = eps @ V_box^T, K=2048 split 16x128 (128 blocks)
    mma_nt<128, 64, 4, 2><<<dim3(CDIM / 64, 1, VSPLIT), 256>>>(
        eps, V_box, vp, 2048 / VSPLIT, DDIM, DDIM, CDIM,
        0, (long long)N_ROIS * CDIM, 2048 / VSPLIT);

    // 3) v = sum of partials
    reduce_v_kernel<<<(N_ROIS * CDIM / 4) / 256, 256>>>();

    // 4) AB partials: [160,256] = exy2 @ W_im^T, K=1024 split 16x64 (192 blocks)
    gemm_nt<<<dim3(ODIM / 64, 3, ABSPLIT), 128>>>(
        exy2, W_im, ABp, ABROWS, ODIM, 1024 / ABSPLIT, 2 * CDIM, 2 * CDIM, ODIM,
        (long long)ABROWS * ODIM, 1024 / ABSPLIT);

    // 5) AB = sum of partials
    reduce_ab_kernel<<<(ABROWS * ODIM / 4) / 256, 256>>>();

    // 6) box[k] = v @ W_box[k]^T : 49 x [128,256], K=512 (196 blocks)
    mma_nt<128, 64, 4, 2><<<dim3(ODIM / 64, 1, KBOX), 256>>>(
        v, W_box, box, CDIM, CDIM, CDIM, ODIM,
        (long long)ODIM * CDIM, (long long)N_ROIS * ODIM, 0);

    // 7) G = box @ AB^T : [6272,160], K=256 (98 blocks)
    mma_nt<64, 160, 2, 4><<<dim3(1, NK / 64, 1), 256>>>(
        box, AB, G, ODIM, ODIM, ODIM, ABROWS, 0, 0, 0);

    // 8) geo = G[:, h] + G[:, 64+w] (154 MB write)
    add_kernel<<<NK, 256>>>(out + idx_off);
}

// round 9
// speedup vs baseline: 3.5430x; 1.0208x over previous
#include <cuda_runtime.h>
#include <cuda_bf16.h>

// ---------------------------------------------------------------------------
// GeometricTerm: geo[n,k,h,w] = G[kn,h] + G[kn,64+w]
// R8: AB stage on tensor cores (mma_nt<64,64,2,4>, padded M=192);
//     G GEMM fused with broadcast-add output; merged reduces. 6 launches.
// ---------------------------------------------------------------------------

#define N_ROIS 128
#define CDIM   512
#define KBOX   49
#define ODIM   256
#define HH     64
#define WW     96
#define DDIM   2048
#define NK     (N_ROIS * KBOX)    // 6272
#define GEO_PER_NK (HH * WW)      // 6144
#define VSPLIT 16
#define ABSPLIT 8
#define ABROWS (HH + WW)          // 160
#define ABPAD  192                // padded row count for 64-row tiles

// scratch (device globals)
__device__ float g_eps [N_ROIS * DDIM];            // [128,2048]
__device__ float g_exy2[ABPAD * 2 * CDIM];         // [192,1024] zero-padded
__device__ float g_vp  [VSPLIT * N_ROIS * CDIM];   // v split-K partials
__device__ float g_v   [N_ROIS * CDIM];            // [128,512]
__device__ float g_ABp [ABSPLIT * ABPAD * ODIM];   // AB split-K partials (192 rows)
__device__ float g_AB  [ABROWS * ODIM];            // [160,256]
__device__ float g_box [KBOX * N_ROIS * ODIM];     // [k,n,o]

// ---------------------------------------------------------------------------
// sinusoid embeddings + zero-padded exy2 + pad rows + indices
// ---------------------------------------------------------------------------
__global__ void embed_kernel(const float* __restrict__ rois,
                             float* __restrict__ out_idx, int write_idx)
{
    const float NEG_L = -6.9077552789821368f / 512.0f;  // -ln(1000)/C
    int b = blockIdx.x;
    if (b < N_ROIS) {
        float z0 = rois[b * 5 + 1], z1 = rois[b * 5 + 2];
        float z2 = rois[b * 5 + 3], z3 = rois[b * 5 + 4];
        for (int t = threadIdx.x; t < DDIM; t += blockDim.x) {
            int j = t >> 9;
            int p = t & 511;
            float z = (j == 0) ? z0 : (j == 1) ? z1 : (j == 2) ? z2 : z3;
            int  s = (p < 256);
            int  e = s ? (2 * p + 1) : (2 * (p - 256));
            float arg = z * __expf(NEG_L * (float)e);
            g_eps[b * DDIM + t] = s ? __sinf(arg) : __cosf(arg);
        }
        if (threadIdx.x == 0 && write_idx) out_idx[b] = rois[b * 5];
    } else if (b < N_ROIS + HH) {
        int h = b - N_ROIS;
        float z = (float)h;
        for (int p = threadIdx.x; p < CDIM; p += blockDim.x) {
            int s = (p < 256);
            int e = s ? (2 * p + 1) : (2 * (p - 256));
            float arg = z * __expf(NEG_L * (float)e);
            g_exy2[h * (2 * CDIM) + p] = s ? __sinf(arg) : __cosf(arg);
            g_exy2[h * (2 * CDIM) + CDIM + p] = 0.f;
        }
    } else if (b < N_ROIS + HH + WW) {
        int w = b - N_ROIS - HH;
        float z = (float)w;
        for (int p = threadIdx.x; p < CDIM; p += blockDim.x) {
            int s = (p < 256);
            int e = s ? (2 * p + 1) : (2 * (p - 256));
            float arg = z * __expf(NEG_L * (float)e);
            g_exy2[(HH + w) * (2 * CDIM) + p] = 0.f;
            g_exy2[(HH + w) * (2 * CDIM) + CDIM + p] = s ? __sinf(arg) : __cosf(arg);
        }
    } else {
        int r = ABROWS + (b - N_ROIS - HH - WW);    // rows 160..191: zero pad
        for (int p = threadIdx.x; p < 2 * CDIM; p += blockDim.x)
            g_exy2[r * (2 * CDIM) + p] = 0.f;
    }
}

// ---------------------------------------------------------------------------
// bf16 split helpers + mma
// ---------------------------------------------------------------------------
__device__ __forceinline__ void split_pack(float x0, float x1,
                                           unsigned& h, unsigned& l)
{
    __nv_bfloat162 hh = __floats2bfloat162_rn(x0, x1);
    float r0 = x0 - __low2float(hh);
    float r1 = x1 - __high2float(hh);
    __nv_bfloat162 ll = __floats2bfloat162_rn(r0, r1);
    h = reinterpret_cast<unsigned&>(hh);
    l = reinterpret_cast<unsigned&>(ll);
}

__device__ __forceinline__ void mma16816(float c[4], const unsigned a[4],
                                         const unsigned b[2])
{
    asm volatile(
        "mma.sync.aligned.m16n8k16.row.col.f32.bf16.bf16.f32 "
        "{%0,%1,%2,%3}, {%4,%5,%6,%7}, {%8,%9}, {%0,%1,%2,%3};"
        : "+f"(c[0]), "+f"(c[1]), "+f"(c[2]), "+f"(c[3])
        : "r"(a[0]), "r"(a[1]), "r"(a[2]), "r"(a[3]), "r"(b[0]), "r"(b[1]));
}

// ---------------------------------------------------------------------------
// NT GEMM via bf16 hi/lo split mma: C[M,N] = A[M,K].B[N,K]^T, fp32 in/out.
// Block tile BM x BN (exact divisors of padded M,N), BK=32, 256 threads.
// Warp grid WM x WN (WM*WN=8); warp tile 32 rows x BN/WN cols.
// z: A += z*kz (split-K), B += z*sB + z*kz, C += z*sC.
// ---------------------------------------------------------------------------
template<int BM, int BN, int WM, int WN>
__global__ __launch_bounds__(256, 2)
void mma_nt(const float* __restrict__ A, const float* __restrict__ B,
            float* __restrict__ C, int K, int lda, int ldb, int ldc,
            long long sB, long long sC, int kz)
{
    constexpr int NI = BN / WN / 8;
    constexpr int P  = 20;

    int z = blockIdx.z;
    A += (long long)z * kz;
    B += (long long)z * sB + (long long)z * kz;
    C += (long long)z * sC;

    __shared__ unsigned As_h[BM * P], As_l[BM * P];
    __shared__ unsigned Bs_h[BN * P], Bs_l[BN * P];

    int tid  = threadIdx.x;
    int lane = tid & 31, wid = tid >> 5;
    int wm = wid % WM, wn = wid / WM;
    int g = lane >> 2, tg = lane & 3;
    int row0 = blockIdx.y * BM;
    int col0 = blockIdx.x * BN;

    float acc[2][NI][4] = {};

    for (int k0 = 0; k0 < K; k0 += 32) {
        float4 ra[BM * 8 / 256], rb[BN * 8 / 256];
#pragma unroll
        for (int j = 0; j < BM * 8 / 256; j++) {
            int i = tid + j * 256, r = i >> 3, c4 = i & 7;
            ra[j] = *(const float4*)(A + (long long)(row0 + r) * lda + k0 + c4 * 4);
        }
#pragma unroll
        for (int j = 0; j < BN * 8 / 256; j++) {
            int i = tid + j * 256, r = i >> 3, c4 = i & 7;
            rb[j] = *(const float4*)(B + (long long)(col0 + r) * ldb + k0 + c4 * 4);
        }
        __syncthreads();
#pragma unroll
        for (int j = 0; j < BM * 8 / 256; j++) {
            int i = tid + j * 256, r = i >> 3, c4 = i & 7;
            unsigned h0, l0, h1, l1;
            split_pack(ra[j].x, ra[j].y, h0, l0);
            split_pack(ra[j].z, ra[j].w, h1, l1);
            As_h[r * P + c4 * 2] = h0; As_h[r * P + c4 * 2 + 1] = h1;
            As_l[r * P + c4 * 2] = l0; As_l[r * P + c4 * 2 + 1] = l1;
        }
#pragma unroll
        for (int j = 0; j < BN * 8 / 256; j++) {
            int i = tid + j * 256, r = i >> 3, c4 = i & 7;
            unsigned h0, l0, h1, l1;
            split_pack(rb[j].x, rb[j].y, h0, l0);
            split_pack(rb[j].z, rb[j].w, h1, l1);
            Bs_h[r * P + c4 * 2] = h0; Bs_h[r * P + c4 * 2 + 1] = h1;
            Bs_l[r * P + c4 * 2] = l0; Bs_l[r * P + c4 * 2 + 1] = l1;
        }
        __syncthreads();

#pragma unroll
        for (int ks = 0; ks < 2; ks++) {
            unsigned ah[2][4], al[2][4], bh[NI][2], bl[NI][2];
#pragma unroll
            for (int mi = 0; mi < 2; mi++) {
                int base = (wm * 32 + mi * 16 + g) * P + ks * 8 + tg;
                ah[mi][0] = As_h[base];           ah[mi][1] = As_h[base + 8 * P];
                ah[mi][2] = As_h[base + 4];       ah[mi][3] = As_h[base + 8 * P + 4];
                al[mi][0] = As_l[base];           al[mi][1] = As_l[base + 8 * P];
                al[mi][2] = As_l[base + 4];       al[mi][3] = As_l[base + 8 * P + 4];
            }
#pragma unroll
            for (int ni = 0; ni < NI; ni++) {
                int base = (wn * (BN / WN) + ni * 8 + g) * P + ks * 8 + tg;
                bh[ni][0] = Bs_h[base]; bh[ni][1] = Bs_h[base + 4];
                bl[ni][0] = Bs_l[base]; bl[ni][1] = Bs_l[base + 4];
            }
#pragma unroll
            for (int mi = 0; mi < 2; mi++)
#pragma unroll
                for (int ni = 0; ni < NI; ni++) {
                    mma16816(acc[mi][ni], ah[mi], bh[ni]);
                    mma16816(acc[mi][ni], ah[mi], bl[ni]);
                    mma16816(acc[mi][ni], al[mi], bh[ni]);
                }
        }
    }

#pragma unroll
    for (int mi = 0; mi < 2; mi++) {
        int r = row0 + wm * 32 + mi * 16 + g;
#pragma unroll
        for (int ni = 0; ni < NI; ni++) {
            int c = col0 + wn * (BN / WN) + ni * 8 + tg * 2;
            *(float2*)(C + (long long)r * ldc + c) =
                make_float2(acc[mi][ni][0], acc[mi][ni][1]);
            *(float2*)(C + (long long)(r + 8) * ldc + c) =
                make_float2(acc[mi][ni][2], acc[mi][ni][3]);
        }
    }
}

// ---------------------------------------------------------------------------
// merged split-K reductions (v: 64 blocks, AB: 40 blocks)
// ---------------------------------------------------------------------------
__global__ void reduce_kernel()
{
    if (blockIdx.x < 64) {
        int i = blockIdx.x * 256 + threadIdx.x;            // [0,16384)
        const float4* vp = (const float4*)g_vp;
        float4 s = vp[i];
#pragma unroll
        for (int j = 1; j < VSPLIT; j++) {
            float4 t = vp[i + j * (N_ROIS * CDIM / 4)];
            s.x += t.x; s.y += t.y; s.z += t.z; s.w += t.w;
        }
        ((float4*)g_v)[i] = s;
    } else {
        int i = (blockIdx.x - 64) * 256 + threadIdx.x;     // [0,10240)
        const float4* p = (const float4*)g_ABp;
        float4 s = p[i];
#pragma unroll
        for (int j = 1; j < ABSPLIT; j++) {
            float4 t = p[i + j * (ABPAD * ODIM / 4)];
            s.x += t.x; s.y += t.y; s.z += t.z; s.w += t.w;
        }
        ((float4*)g_AB)[i] = s;
    }
}

// ---------------------------------------------------------------------------
// Fused G GEMM + broadcast-add output.
// G tile = box[row0:row0+64] @ AB^T  ([64,160], K=256), staged to smem, then
// geo[nk,h,w] = G[r,h] + G[r,64+w] written directly (24 KB per row).
// ---------------------------------------------------------------------------
__global__ __launch_bounds__(256, 2)
void g_add_kernel(const float* __restrict__ A,   // box [6272,256]
                  const float* __restrict__ B,   // AB  [160,256]
                  float* __restrict__ out)
{
    constexpr int BM = 64, BN = 160, WM = 2, WN = 4, NI = 5, P = 20;
    constexpr int KK = 256, LDA = 256, LDB = 256;

    __shared__ float sbuf[BM * 161];               // 41216 B, aliased below
    unsigned* As_h = (unsigned*)sbuf;              // [BM*P]
    unsigned* As_l = As_h + BM * P;
    unsigned* Bs_h = As_l + BM * P;
    unsigned* Bs_l = Bs_h + BN * P;                // total 8960 u32 <= 10304

    int tid  = threadIdx.x;
    int lane = tid & 31, wid = tid >> 5;
    int wm = wid % WM, wn = wid / WM;
    int g = lane >> 2, tg = lane & 3;
    int row0 = blockIdx.y * BM;

    float acc[2][NI][4] = {};

    for (int k0 = 0; k0 < KK; k0 += 32) {
        float4 ra[2], rb[5];
#pragma unroll
        for (int j = 0; j < 2; j++) {
            int i = tid + j * 256, r = i >> 3, c4 = i & 7;
            ra[j] = *(const float4*)(A + (long long)(row0 + r) * LDA + k0 + c4 * 4);
        }
#pragma unroll
        for (int j = 0; j < 5; j++) {
            int i = tid + j * 256, r = i >> 3, c4 = i & 7;
            rb[j] = *(const float4*)(B + (long long)r * LDB + k0 + c4 * 4);
        }
        __syncthreads();
#pragma unroll
        for (int j = 0; j < 2; j++) {
            int i = tid + j * 256, r = i >> 3, c4 = i & 7;
            unsigned h0, l0, h1, l1;
            split_pack(ra[j].x, ra[j].y, h0, l0);
            split_pack(ra[j].z, ra[j].w, h1, l1);
            As_h[r * P + c4 * 2] = h0; As_h[r * P + c4 * 2 + 1] = h1;
            As_l[r * P + c4 * 2] = l0; As_l[r * P + c4 * 2 + 1] = l1;
        }
#pragma unroll
        for (int j = 0; j < 5; j++) {
            int i = tid + j * 256, r = i >> 3, c4 = i & 7;
            unsigned h0, l0, h1, l1;
            split_pack(rb[j].x, rb[j].y, h0, l0);
            split_pack(rb[j].z, rb[j].w, h1, l1);
            Bs_h[r * P + c4 * 2] = h0; Bs_h[r * P + c4 * 2 + 1] = h1;
            Bs_l[r * P + c4 * 2] = l0; Bs_l[r * P + c4 * 2 + 1] = l1;
        }
        __syncthreads();

#pragma unroll
        for (int ks = 0; ks < 2; ks++) {
            unsigned ah[2][4], al[2][4], bh[NI][2], bl[NI][2];
#pragma unroll
            for (int mi = 0; mi < 2; mi++) {
                int base = (wm * 32 + mi * 16 + g) * P + ks * 8 + tg;
                ah[mi][0] = As_h[base];           ah[mi][1] = As_h[base + 8 * P];
                ah[mi][2] = As_h[base + 4];       ah[mi][3] = As_h[base + 8 * P + 4];
                al[mi][0] = As_l[base];           al[mi][1] = As_l[base + 8 * P];
                al[mi][2] = As_l[base + 4];       al[mi][3] = As_l[base + 8 * P + 4];
            }
#pragma unroll
            for (int ni = 0; ni < NI; ni++) {
                int base = (wn * (BN / WN) + ni * 8 + g) * P + ks * 8 + tg;
                bh[ni][0] = Bs_h[base]; bh[ni][1] = Bs_h[base + 4];
                bl[ni][0] = Bs_l[base]; bl[ni][1] = Bs_l[base + 4];
            }
#pragma unroll
            for (int mi = 0; mi < 2; mi++)
#pragma unroll
                for (int ni = 0; ni < NI; ni++) {
                    mma16816(acc[mi][ni], ah[mi], bh[ni]);
                    mma16816(acc[mi][ni], ah[mi], bl[ni]);
                    mma16816(acc[mi][ni], al[mi], bh[ni]);
                }
        }
    }

    __syncthreads();   // done with tiles; sbuf becomes Gs[64][161]

    // stage G tile to smem
#pragma unroll
    for (int mi = 0; mi < 2; mi++) {
        int r = wm * 32 + mi * 16 + g;
#pragma unroll
        for (int ni = 0; ni < NI; ni++) {
            int c = wn * (BN / WN) + ni * 8 + tg * 2;
            sbuf[r * 161 + c]           = acc[mi][ni][0];
            sbuf[r * 161 + c + 1]       = acc[mi][ni][1];
            sbuf[(r + 8) * 161 + c]     = acc[mi][ni][2];
            sbuf[(r + 8) * 161 + c + 1] = acc[mi][ni][3];
        }
    }
    __syncthreads();

    // broadcast-add write: row r -> output tile (n*KBOX+k), kn = row0 + r
    for (int r = 0; r < BM; r++) {
        const float* gr = sbuf + r * 161;
        int kn = row0 + r;
        int k = kn >> 7;          // kn / 128
        int n = kn & 127;
        float4* o = (float4*)(out + (long long)(n * KBOX + k) * GEO_PER_NK);
#pragma unroll
        for (int jj = 0; jj < GEO_PER_NK / 4 / 256; jj++) {
            int j = tid + jj * 256;
            int h = j / 24;
            int w = (j - h * 24) * 4;
            float ga = gr[h];
            float4 v4;
            v4.x = ga + gr[64 + w + 0];
            v4.y = ga + gr[64 + w + 1];
            v4.z = ga + gr[64 + w + 2];
            v4.w = ga + gr[64 + w + 3];
            o[j] = v4;
        }
    }
}

// ---------------------------------------------------------------------------
extern "C" void kernel_launch(void* const* d_in, const int* in_sizes, int n_in,
                              void* d_out, int out_size)
{
    const float* rois  = (const float*)d_in[1];
    const float* V_box = (const float*)d_in[2];
    const float* W_box = (const float*)d_in[3];
    const float* W_im  = (const float*)d_in[4];
    float* out = (float*)d_out;

    const long long n_geo = (long long)NK * GEO_PER_NK;   // 38,535,168
    long long idx_off = (long long)out_size - n_geo;
    if (idx_off < 0) idx_off = 0;

    float *eps, *exy2, *vp, *v, *ABp, *AB, *box;
    cudaGetSymbolAddress((void**)&eps,  g_eps);
    cudaGetSymbolAddress((void**)&exy2, g_exy2);
    cudaGetSymbolAddress((void**)&vp,   g_vp);
    cudaGetSymbolAddress((void**)&v,    g_v);
    cudaGetSymbolAddress((void**)&ABp,  g_ABp);
    cudaGetSymbolAddress((void**)&AB,   g_AB);
    cudaGetSymbolAddress((void**)&box,  g_box);

    // 1) embeddings (+ indices, + exy2 zero pad rows)
    embed_kernel<<<N_ROIS + HH + WW + (ABPAD - ABROWS), 256>>>(
        rois, out, idx_off >= N_ROIS ? 1 : 0);

    // 2) v partials: [128,512] = eps @ V_box^T, K=2048 split 16x128 (128 blocks)
    mma_nt<128, 64, 4, 2><<<dim3(CDIM / 64, 1, VSPLIT), 256>>>(
        eps, V_box, vp, 2048 / VSPLIT, DDIM, DDIM, CDIM,
        0, (long long)N_ROIS * CDIM, 2048 / VSPLIT);

    // 3) AB partials: [192,256] = exy2 @ W_im^T, K=1024 split 8x128 (96 blocks)
    mma_nt<64, 64, 2, 4><<<dim3(ODIM / 64, ABPAD / 64, ABSPLIT), 256>>>(
        exy2, W_im, ABp, 1024 / ABSPLIT, 2 * CDIM, 2 * CDIM, ODIM,
        0, (long long)ABPAD * ODIM, 1024 / ABSPLIT);

    // 4) merged reductions (v: 64 blocks, AB: 40 blocks)
    reduce_kernel<<<104, 256>>>();

    // 5) box[k] = v @ W_box[k]^T : 49 x [128,256], K=512 (196 blocks)
    mma_nt<128, 64, 4, 2><<<dim3(ODIM / 64, 1, KBOX), 256>>>(
        v, W_box, box, CDIM, CDIM, CDIM, ODIM,
        (long long)ODIM * CDIM, (long long)N_ROIS * ODIM, 0);

    // 6) fused G GEMM + broadcast-add (98 blocks; writes 154 MB)
    g_add_kernel<<<dim3(1, NK / 64, 1), 256>>>(box, AB, out + idx_off);
}

// round 10
// speedup vs baseline: 3.7570x; 1.0604x over previous
#include <cuda_runtime.h>
#include <cuda_bf16.h>

// ---------------------------------------------------------------------------
// GeometricTerm: geo[n,k,h,w] = G[kn,h] + G[kn,64+w]
// R9: wide 6272-block output writer restored (R8 fusion starved DRAM width);
//     split-K reduces replaced by atomicAdd epilogues (zeroed in embed).
// ---------------------------------------------------------------------------

#define N_ROIS 128
#define CDIM   512
#define KBOX   49
#define ODIM   256
#define HH     64
#define WW     96
#define DDIM   2048
#define NK     (N_ROIS * KBOX)    // 6272
#define GEO_PER_NK (HH * WW)      // 6144
#define VSPLIT 16
#define ABSPLIT 8
#define ABROWS (HH + WW)          // 160
#define ABPAD  192                // padded row count for 64-row tiles

// scratch (device globals)
__device__ float g_eps [N_ROIS * DDIM];            // [128,2048]
__device__ float g_exy2[ABPAD * 2 * CDIM];         // [192,1024] zero-padded
__device__ float g_v   [N_ROIS * CDIM];            // [128,512]  (atomic accum)
__device__ float g_AB  [ABPAD * ODIM];             // [192,256]  (atomic accum)
__device__ float g_box [KBOX * N_ROIS * ODIM];     // [k,n,o]
__device__ float g_G   [NK * ABROWS];              // [kn,160]

#define ZERO_BLOCKS 64
#define ZERO_FLOATS (N_ROIS * CDIM + ABPAD * ODIM)   // 65536 + 49152 = 114688

// ---------------------------------------------------------------------------
// sinusoid embeddings + zero-padded exy2 + pad rows + indices + accum zeroing
// ---------------------------------------------------------------------------
__global__ void embed_kernel(const float* __restrict__ rois,
                             float* __restrict__ out_idx, int write_idx)
{
    const float NEG_L = -6.9077552789821368f / 512.0f;  // -ln(1000)/C
    int b = blockIdx.x;
    if (b < N_ROIS) {
        float z0 = rois[b * 5 + 1], z1 = rois[b * 5 + 2];
        float z2 = rois[b * 5 + 3], z3 = rois[b * 5 + 4];
        for (int t = threadIdx.x; t < DDIM; t += blockDim.x) {
            int j = t >> 9;
            int p = t & 511;
            float z = (j == 0) ? z0 : (j == 1) ? z1 : (j == 2) ? z2 : z3;
            int  s = (p < 256);
            int  e = s ? (2 * p + 1) : (2 * (p - 256));
            float arg = z * __expf(NEG_L * (float)e);
            g_eps[b * DDIM + t] = s ? __sinf(arg) : __cosf(arg);
        }
        if (threadIdx.x == 0 && write_idx) out_idx[b] = rois[b * 5];
    } else if (b < N_ROIS + HH) {
        int h = b - N_ROIS;
        float z = (float)h;
        for (int p = threadIdx.x; p < CDIM; p += blockDim.x) {
            int s = (p < 256);
            int e = s ? (2 * p + 1) : (2 * (p - 256));
            float arg = z * __expf(NEG_L * (float)e);
            g_exy2[h * (2 * CDIM) + p] = s ? __sinf(arg) : __cosf(arg);
            g_exy2[h * (2 * CDIM) + CDIM + p] = 0.f;
        }
    } else if (b < N_ROIS + HH + WW) {
        int w = b - N_ROIS - HH;
        float z = (float)w;
        for (int p = threadIdx.x; p < CDIM; p += blockDim.x) {
            int s = (p < 256);
            int e = s ? (2 * p + 1) : (2 * (p - 256));
            float arg = z * __expf(NEG_L * (float)e);
            g_exy2[(HH + w) * (2 * CDIM) + p] = 0.f;
            g_exy2[(HH + w) * (2 * CDIM) + CDIM + p] = s ? __sinf(arg) : __cosf(arg);
        }
    } else if (b < N_ROIS + HH + WW + (ABPAD - ABROWS)) {
        int r = ABROWS + (b - N_ROIS - HH - WW);    // rows 160..191: zero pad
        for (int p = threadIdx.x; p < 2 * CDIM; p += blockDim.x)
            g_exy2[r * (2 * CDIM) + p] = 0.f;
    } else {
        // zero the atomic accumulators g_v and g_AB (float4 stores)
        int zb = b - (N_ROIS + HH + WW + (ABPAD - ABROWS));
        for (int i = zb * 256 + threadIdx.x; i < ZERO_FLOATS / 4;
             i += ZERO_BLOCKS * 256) {
            if (i < N_ROIS * CDIM / 4)
                ((float4*)g_v)[i] = make_float4(0.f, 0.f, 0.f, 0.f);
            else
                ((float4*)g_AB)[i - N_ROIS * CDIM / 4] =
                    make_float4(0.f, 0.f, 0.f, 0.f);
        }
    }
}

// ---------------------------------------------------------------------------
// bf16 split helpers + mma
// ---------------------------------------------------------------------------
__device__ __forceinline__ void split_pack(float x0, float x1,
                                           unsigned& h, unsigned& l)
{
    __nv_bfloat162 hh = __floats2bfloat162_rn(x0, x1);
    float r0 = x0 - __low2float(hh);
    float r1 = x1 - __high2float(hh);
    __nv_bfloat162 ll = __floats2bfloat162_rn(r0, r1);
    h = reinterpret_cast<unsigned&>(hh);
    l = reinterpret_cast<unsigned&>(ll);
}

__device__ __forceinline__ void mma16816(float c[4], const unsigned a[4],
                                         const unsigned b[2])
{
    asm volatile(
        "mma.sync.aligned.m16n8k16.row.col.f32.bf16.bf16.f32 "
        "{%0,%1,%2,%3}, {%4,%5,%6,%7}, {%8,%9}, {%0,%1,%2,%3};"
        : "+f"(c[0]), "+f"(c[1]), "+f"(c[2]), "+f"(c[3])
        : "r"(a[0]), "r"(a[1]), "r"(a[2]), "r"(a[3]), "r"(b[0]), "r"(b[1]));
}

// ---------------------------------------------------------------------------
// NT GEMM via bf16 hi/lo split mma: C[M,N] = A[M,K].B[N,K]^T, fp32 in/out.
// Block tile BM x BN, BK=32, 256 threads. Warp grid WM x WN (WM*WN=8).
// z: A += z*kz (split-K), B += z*sB + z*kz, C += z*sC.
// ATOMIC: epilogue uses atomicAdd (for split-K accumulation into shared C).
// ---------------------------------------------------------------------------
template<int BM, int BN, int WM, int WN, bool ATOMIC>
__global__ __launch_bounds__(256, 2)
void mma_nt(const float* __restrict__ A, const float* __restrict__ B,
            float* __restrict__ C, int K, int lda, int ldb, int ldc,
            long long sB, long long sC, int kz)
{
    constexpr int NI = BN / WN / 8;
    constexpr int P  = 20;

    int z = blockIdx.z;
    A += (long long)z * kz;
    B += (long long)z * sB + (long long)z * kz;
    C += (long long)z * sC;

    __shared__ unsigned As_h[BM * P], As_l[BM * P];
    __shared__ unsigned Bs_h[BN * P], Bs_l[BN * P];

    int tid  = threadIdx.x;
    int lane = tid & 31, wid = tid >> 5;
    int wm = wid % WM, wn = wid / WM;
    int g = lane >> 2, tg = lane & 3;
    int row0 = blockIdx.y * BM;
    int col0 = blockIdx.x * BN;

    float acc[2][NI][4] = {};

    for (int k0 = 0; k0 < K; k0 += 32) {
        float4 ra[BM * 8 / 256], rb[BN * 8 / 256];
#pragma unroll
        for (int j = 0; j < BM * 8 / 256; j++) {
            int i = tid + j * 256, r = i >> 3, c4 = i & 7;
            ra[j] = *(const float4*)(A + (long long)(row0 + r) * lda + k0 + c4 * 4);
        }
#pragma unroll
        for (int j = 0; j < BN * 8 / 256; j++) {
            int i = tid + j * 256, r = i >> 3, c4 = i & 7;
            rb[j] = *(const float4*)(B + (long long)(col0 + r) * ldb + k0 + c4 * 4);
        }
        __syncthreads();
#pragma unroll
        for (int j = 0; j < BM * 8 / 256; j++) {
            int i = tid + j * 256, r = i >> 3, c4 = i & 7;
            unsigned h0, l0, h1, l1;
            split_pack(ra[j].x, ra[j].y, h0, l0);
            split_pack(ra[j].z, ra[j].w, h1, l1);
            As_h[r * P + c4 * 2] = h0; As_h[r * P + c4 * 2 + 1] = h1;
            As_l[r * P + c4 * 2] = l0; As_l[r * P + c4 * 2 + 1] = l1;
        }
#pragma unroll
        for (int j = 0; j < BN * 8 / 256; j++) {
            int i = tid + j * 256, r = i >> 3, c4 = i & 7;
            unsigned h0, l0, h1, l1;
            split_pack(rb[j].x, rb[j].y, h0, l0);
            split_pack(rb[j].z, rb[j].w, h1, l1);
            Bs_h[r * P + c4 * 2] = h0; Bs_h[r * P + c4 * 2 + 1] = h1;
            Bs_l[r * P + c4 * 2] = l0; Bs_l[r * P + c4 * 2 + 1] = l1;
        }
        __syncthreads();

#pragma unroll
        for (int ks = 0; ks < 2; ks++) {
            unsigned ah[2][4], al[2][4], bh[NI][2], bl[NI][2];
#pragma unroll
            for (int mi = 0; mi < 2; mi++) {
                int base = (wm * 32 + mi * 16 + g) * P + ks * 8 + tg;
                ah[mi][0] = As_h[base];           ah[mi][1] = As_h[base + 8 * P];
                ah[mi][2] = As_h[base + 4];       ah[mi][3] = As_h[base + 8 * P + 4];
                al[mi][0] = As_l[base];           al[mi][1] = As_l[base + 8 * P];
                al[mi][2] = As_l[base + 4];       al[mi][3] = As_l[base + 8 * P + 4];
            }
#pragma unroll
            for (int ni = 0; ni < NI; ni++) {
                int base = (wn * (BN / WN) + ni * 8 + g) * P + ks * 8 + tg;
                bh[ni][0] = Bs_h[base]; bh[ni][1] = Bs_h[base + 4];
                bl[ni][0] = Bs_l[base]; bl[ni][1] = Bs_l[base + 4];
            }
#pragma unroll
            for (int mi = 0; mi < 2; mi++)
#pragma unroll
                for (int ni = 0; ni < NI; ni++) {
                    mma16816(acc[mi][ni], ah[mi], bh[ni]);
                    mma16816(acc[mi][ni], ah[mi], bl[ni]);
                    mma16816(acc[mi][ni], al[mi], bh[ni]);
                }
        }
    }

#pragma unroll
    for (int mi = 0; mi < 2; mi++) {
        int r = row0 + wm * 32 + mi * 16 + g;
#pragma unroll
        for (int ni = 0; ni < NI; ni++) {
            int c = col0 + wn * (BN / WN) + ni * 8 + tg * 2;
            if (ATOMIC) {
                atomicAdd(C + (long long)r * ldc + c,           acc[mi][ni][0]);
                atomicAdd(C + (long long)r * ldc + c + 1,       acc[mi][ni][1]);
                atomicAdd(C + (long long)(r + 8) * ldc + c,     acc[mi][ni][2]);
                atomicAdd(C + (long long)(r + 8) * ldc + c + 1, acc[mi][ni][3]);
            } else {
                *(float2*)(C + (long long)r * ldc + c) =
                    make_float2(acc[mi][ni][0], acc[mi][ni][1]);
                *(float2*)(C + (long long)(r + 8) * ldc + c) =
                    make_float2(acc[mi][ni][2], acc[mi][ni][3]);
            }
        }
    }
}

// ---------------------------------------------------------------------------
// geo[nk,h,w] = G[kn,h] + G[kn,64+w]  -- 6272 blocks, pure streaming write
// ---------------------------------------------------------------------------
__global__ void add_kernel(float* __restrict__ out)
{
    int nk = blockIdx.x;
    int n = nk / KBOX;
    int k = nk - n * KBOX;
    int kn = k * N_ROIS + n;

    __shared__ float ga[HH];
    __shared__ float gb[WW];
    int t = threadIdx.x;
    if (t < HH)            ga[t]      = g_G[kn * ABROWS + t];
    else if (t < ABROWS)   gb[t - HH] = g_G[kn * ABROWS + t];
    __syncthreads();

    float4* o = (float4*)(out + (long long)nk * GEO_PER_NK);
    for (int j = t; j < GEO_PER_NK / 4; j += blockDim.x) {
        int h = j / 24;
        int w = (j - h * 24) * 4;
        float g = ga[h];
        float4 v;
        v.x = g + gb[w + 0];
        v.y = g + gb[w + 1];
        v.z = g + gb[w + 2];
        v.w = g + gb[w + 3];
        o[j] = v;
    }
}

// ---------------------------------------------------------------------------
extern "C" void kernel_launch(void* const* d_in, const int* in_sizes, int n_in,
                              void* d_out, int out_size)
{
    const float* rois  = (const float*)d_in[1];
    const float* V_box = (const float*)d_in[2];
    const float* W_box = (const float*)d_in[3];
    const float* W_im  = (const float*)d_in[4];
    float* out = (float*)d_out;

    const long long n_geo = (long long)NK * GEO_PER_NK;   // 38,535,168
    long long idx_off = (long long)out_size - n_geo;
    if (idx_off < 0) idx_off = 0;

    float *eps, *exy2, *v, *AB, *box, *G;
    cudaGetSymbolAddress((void**)&eps,  g_eps);
    cudaGetSymbolAddress((void**)&exy2, g_exy2);
    cudaGetSymbolAddress((void**)&v,    g_v);
    cudaGetSymbolAddress((void**)&AB,   g_AB);
    cudaGetSymbolAddress((void**)&box,  g_box);
    cudaGetSymbolAddress((void**)&G,    g_G);

    // 1) embeddings (+ indices, + exy2 pad, + zero accumulators)
    embed_kernel<<<N_ROIS + HH + WW + (ABPAD - ABROWS) + ZERO_BLOCKS, 256>>>(
        rois, out, idx_off >= N_ROIS ? 1 : 0);

    // 2) v = eps @ V_box^T, K=2048 split 16x128, atomic accum (128 blocks)
    mma_nt<128, 64, 4, 2, true><<<dim3(CDIM / 64, 1, VSPLIT), 256>>>(
        eps, V_box, v, 2048 / VSPLIT, DDIM, DDIM, CDIM,
        0, 0, 2048 / VSPLIT);

    // 3) AB = exy2 @ W_im^T, K=1024 split 8x128, atomic accum (96 blocks)
    mma_nt<64, 64, 2, 4, true><<<dim3(ODIM / 64, ABPAD / 64, ABSPLIT), 256>>>(
        exy2, W_im, AB, 1024 / ABSPLIT, 2 * CDIM, 2 * CDIM, ODIM,
        0, 0, 1024 / ABSPLIT);

    // 4) box[k] = v @ W_box[k]^T : 49 x [128,256], K=512 (196 blocks)
    mma_nt<128, 64, 4, 2, false><<<dim3(ODIM / 64, 1, KBOX), 256>>>(
        v, W_box, box, CDIM, CDIM, CDIM, ODIM,
        (long long)ODIM * CDIM, (long long)N_ROIS * ODIM, 0);

    // 5) G = box @ AB^T : [6272,160], K=256 (98 blocks)
    mma_nt<64, 160, 2, 4, false><<<dim3(1, NK / 64, 1), 256>>>(
        box, AB, G, ODIM, ODIM, ODIM, ABROWS, 0, 0, 0);

    // 6) geo = G[:, h] + G[:, 64+w]  (6272 blocks, 154 MB write)
    add_kernel<<<NK, 256>>>(out + idx_off);
}